// round 2
// baseline (speedup 1.0000x reference)
#include <cuda_runtime.h>
#include <math.h>
#include <stdint.h>

// Problem constants
static constexpr int BB   = 64;    // batch
static constexpr int LL   = 128;   // seq len
static constexpr int EMBD = 300;
static constexpr int HH   = 256;
static constexpr int NE   = 34;    // NUM_EVENTS
static constexpr int NA   = 36;    // NUM_ARGS

// ---------------- scratch (device globals; no runtime alloc) ----------------
__device__ float g_x   [LL * BB * EMBD];        // [t][b][e]
__device__ float g_xg  [LL * BB * 2048];        // [t][b][dir*1024+row]
__device__ float g_hs  [BB * LL * 512];         // [b][t][dir*256+u]
__device__ float g_c   [2 * BB * HH];           // [dir][b][u]
__device__ float g_evbase[BB * LL * NE];        // hs @ We[:, :512]^T + be
__device__ float g_base36[BB * LL * NA];        // hs @ Wa[:, :512]^T + ba
__device__ float g_thadd [BB * LL * NA];        // hs @ Wa[:,512:1024]^T
__device__ float g_Wcat [112 * 512];            // packed [We|Wa_hs|Wa_th] rows (pad to 112)
__device__ float g_WeGT [33 * 34];              // We[:,512+j] transposed
__device__ float g_WaGT [35 * 36];              // Wa[:,1024+j] transposed
__device__ unsigned char g_emask[BB * LL];      // ev_pred > 0 per (b, t)

// ---------------- kernel 1: embedding gather -> x[t][b][:] ----------------
__global__ void k_gather(const int* __restrict__ ids, const float* __restrict__ emb) {
    int bx = blockIdx.x;          // bx = t*64 + b
    int t = bx >> 6;
    int b = bx & 63;
    int id = ids[b * LL + t];
    const float4* src = (const float4*)(emb + (size_t)id * EMBD);
    float4* dst = (float4*)(g_x + (size_t)bx * EMBD);
    int i = threadIdx.x;
    if (i < 75) dst[i] = src[i];  // 300 floats = 75 float4
}

// ---------------- kernel 2: pack decode weights ----------------
__global__ void k_prep(const float* __restrict__ We, const float* __restrict__ Wa) {
    int tid = blockIdx.x * blockDim.x + threadIdx.x;
    int stride = gridDim.x * blockDim.x;
    for (int i = tid; i < 112 * 512; i += stride) {
        int n = i >> 9, k = i & 511;
        float v = 0.f;
        if (n < 34)       v = We[n * 545 + k];
        else if (n < 70)  v = Wa[(n - 34) * 1059 + k];
        else if (n < 106) v = Wa[(n - 70) * 1059 + 512 + k];
        g_Wcat[i] = v;
    }
    for (int i = tid; i < 33 * 34; i += stride) {
        int j = i / 34, e = i % 34;
        g_WeGT[i] = We[e * 545 + 512 + j];
    }
    for (int i = tid; i < 35 * 36; i += stride) {
        int j = i / 36, e = i % 36;
        g_WaGT[i] = Wa[e * 1059 + 1024 + j];
    }
}

// ---------------- kernel 3: input GEMM  xg = x @ [W_ih_f|W_ih_b]^T + bias ----------------
// M=8192 (m = t*64+b), N=2048 (n = dir*1024 + row), K=300. 64x64 tile, 4x4/thread.
__global__ void k_gemm1(const float* __restrict__ Wf, const float* __restrict__ Wb,
                        const float* __restrict__ bf, const float* __restrict__ bbv) {
    __shared__ float Ash[20][68];
    __shared__ float Bsh[20][68];
    int n0 = blockIdx.x * 64;
    int m0 = blockIdx.y * 64;
    int dir = n0 >> 10;
    int j0 = n0 & 1023;
    const float* W    = dir ? Wb  : Wf;
    const float* bias = dir ? bbv : bf;
    int tid = threadIdx.x;
    int tm = tid & 15, tn = tid >> 4;
    float acc[4][4] = {};
    for (int kt = 0; kt < 15; kt++) {
        int k0 = kt * 20;
#pragma unroll
        for (int i = 0; i < 5; i++) {
            int idx = i * 256 + tid;
            int r = idx / 20, kk = idx % 20;
            Ash[kk][r] = g_x[(size_t)(m0 + r) * EMBD + k0 + kk];
            Bsh[kk][r] = W[(size_t)(j0 + r) * EMBD + k0 + kk];
        }
        __syncthreads();
#pragma unroll
        for (int kk = 0; kk < 20; kk++) {
            float4 a = *(float4*)&Ash[kk][tm * 4];
            float4 bv = *(float4*)&Bsh[kk][tn * 4];
            acc[0][0] += a.x * bv.x; acc[0][1] += a.x * bv.y; acc[0][2] += a.x * bv.z; acc[0][3] += a.x * bv.w;
            acc[1][0] += a.y * bv.x; acc[1][1] += a.y * bv.y; acc[1][2] += a.y * bv.z; acc[1][3] += a.y * bv.w;
            acc[2][0] += a.z * bv.x; acc[2][1] += a.z * bv.y; acc[2][2] += a.z * bv.z; acc[2][3] += a.z * bv.w;
            acc[3][0] += a.w * bv.x; acc[3][1] += a.w * bv.y; acc[3][2] += a.w * bv.z; acc[3][3] += a.w * bv.w;
        }
        __syncthreads();
    }
    float b0 = bias[j0 + tn * 4 + 0], b1 = bias[j0 + tn * 4 + 1];
    float b2 = bias[j0 + tn * 4 + 2], b3 = bias[j0 + tn * 4 + 3];
#pragma unroll
    for (int i = 0; i < 4; i++) {
        int m = m0 + tm * 4 + i;
        float4 o;
        o.x = acc[i][0] + b0; o.y = acc[i][1] + b1; o.z = acc[i][2] + b2; o.w = acc[i][3] + b3;
        *(float4*)&g_xg[(size_t)m * 2048 + n0 + tn * 4] = o;
    }
}

// ---------------- kernel 4: one LSTM timestep (both directions) ----------------
// 128 blocks: dir = bx>>6, 4 hidden units each, all 64 batches. 256 threads.
// Gate tile per block: 16 rows (4 gates x 4 units) x 64 batches.
// 256 threads = 8 row-pairs x 32 batch-pairs, each thread 2x2.
__global__ void k_lstm_step(const float* __restrict__ Whf, const float* __restrict__ Whb, int s) {
    extern __shared__ float sm[];
    float* hsh = sm;              // [256][66]  h_prev transposed (k-major)
    float* wsh = sm + 256 * 66;   // [256][18]  W rows, k-major (16 rows used)
    float* gsh = wsh + 256 * 18;  // [16][64]   gate pre-activations
    int bx = blockIdx.x;
    int dir = bx >> 6;
    int u0 = (bx & 63) * 4;
    int t = dir ? (LL - 1 - s) : s;
    int tprev = dir ? (t + 1) : (t - 1);
    const float* W = dir ? Whb : Whf;
    int tid = threadIdx.x;

#pragma unroll
    for (int i = 0; i < 16; i++) {                   // W: 16 rows x 256
        int idx = i * 256 + tid;
        int lr = idx >> 8;                           // local row: g*4 + uu
        int k  = idx & 255;
        int g = lr >> 2, uu = lr & 3;
        wsh[k * 18 + lr] = W[(size_t)(g * HH + u0 + uu) * HH + k];
    }
    if (s > 0) {
#pragma unroll
        for (int i = 0; i < 16; i++) {               // h_prev: 64 b x 256 k (float4)
            int idx4 = i * 256 + tid;
            int b = idx4 >> 6;
            int k4 = (idx4 & 63) * 4;
            float4 hv = *(const float4*)&g_hs[(size_t)(b * LL + tprev) * 512 + dir * HH + k4];
            hsh[(k4 + 0) * 66 + b] = hv.x;
            hsh[(k4 + 1) * 66 + b] = hv.y;
            hsh[(k4 + 2) * 66 + b] = hv.z;
            hsh[(k4 + 3) * 66 + b] = hv.w;
        }
    }
    __syncthreads();

    float a00 = 0.f, a01 = 0.f, a10 = 0.f, a11 = 0.f;
    int br  = tid >> 5;  // row pair   0..7  -> rows 2br, 2br+1 (of 16)
    int bbp = tid & 31;  // batch pair 0..31 -> batches 2bbp, 2bbp+1 (of 64)
    if (s > 0) {
#pragma unroll 8
        for (int k = 0; k < HH; k++) {
            float2 w = *(float2*)&wsh[k * 18 + br * 2];
            float2 h = *(float2*)&hsh[k * 66 + bbp * 2];
            a00 += w.x * h.x; a01 += w.x * h.y;
            a10 += w.y * h.x; a11 += w.y * h.y;
        }
    }
    gsh[(br * 2 + 0) * 64 + bbp * 2 + 0] = a00;
    gsh[(br * 2 + 0) * 64 + bbp * 2 + 1] = a01;
    gsh[(br * 2 + 1) * 64 + bbp * 2 + 0] = a10;
    gsh[(br * 2 + 1) * 64 + bbp * 2 + 1] = a11;
    __syncthreads();

    int uu = tid >> 6;
    int b = tid & 63;
    int u = u0 + uu;
    size_t xb = (size_t)(t * BB + b) * 2048 + dir * 1024 + u;
    float gi = gsh[(0 * 4 + uu) * 64 + b] + g_xg[xb + 0 * HH];
    float gf = gsh[(1 * 4 + uu) * 64 + b] + g_xg[xb + 1 * HH];
    float gg = gsh[(2 * 4 + uu) * 64 + b] + g_xg[xb + 2 * HH];
    float go = gsh[(3 * 4 + uu) * 64 + b] + g_xg[xb + 3 * HH];
    float c = (s > 0) ? g_c[(dir * BB + b) * HH + u] : 0.f;
    float si = 1.f / (1.f + expf(-gi));
    float sf = 1.f / (1.f + expf(-gf));
    float so = 1.f / (1.f + expf(-go));
    c = sf * c + si * tanhf(gg);
    float h = so * tanhf(c);
    g_c[(dir * BB + b) * HH + u] = c;
    g_hs[(size_t)(b * LL + t) * 512 + dir * HH + u] = h;
}

// ---------------- kernel 5: projection GEMM  hs[8192,512] @ Wcat^T[512,112] ----------------
__global__ void k_gemm2(const float* __restrict__ be, const float* __restrict__ ba) {
    __shared__ float Ash[16][68];
    __shared__ float Bsh[16][116];
    int m0 = blockIdx.x * 64;
    int tid = threadIdx.x;
    int tm = tid & 15, tn = tid >> 4;
    float acc[4][7] = {};
    for (int kt = 0; kt < 32; kt++) {
        int k0 = kt * 16;
#pragma unroll
        for (int i = 0; i < 4; i++) {
            int idx = i * 256 + tid;
            int mm = idx >> 4, kk = idx & 15;
            Ash[kk][mm] = g_hs[(size_t)(m0 + mm) * 512 + k0 + kk];
        }
#pragma unroll
        for (int i = 0; i < 7; i++) {
            int idx = i * 256 + tid;
            int nn = idx >> 4, kk = idx & 15;
            Bsh[kk][nn] = g_Wcat[(size_t)nn * 512 + k0 + kk];
        }
        __syncthreads();
#pragma unroll
        for (int kk = 0; kk < 16; kk++) {
            float4 a = *(float4*)&Ash[kk][tm * 4];
#pragma unroll
            for (int j = 0; j < 7; j++) {
                float bv = Bsh[kk][tn * 7 + j];
                acc[0][j] += a.x * bv;
                acc[1][j] += a.y * bv;
                acc[2][j] += a.z * bv;
                acc[3][j] += a.w * bv;
            }
        }
        __syncthreads();
    }
#pragma unroll
    for (int i = 0; i < 4; i++) {
        int m = m0 + tm * 4 + i;
#pragma unroll
        for (int j = 0; j < 7; j++) {
            int n = tn * 7 + j;
            float v = acc[i][j];
            if (n < 34)       g_evbase[(size_t)m * NE + n]        = v + be[n];
            else if (n < 70)  g_base36[(size_t)m * NA + (n - 34)] = v + ba[n - 34];
            else if (n < 106) g_thadd [(size_t)m * NA + (n - 70)] = v;
        }
    }
}

// ---------------- kernel 6 (stage A): 64 independent event chains ----------------
__global__ void k_stageA(float* __restrict__ out_ev) {
    int b = threadIdx.x;   // 64 threads
    float ctrg[NE];
#pragma unroll
    for (int e = 0; e < NE; e++) ctrg[e] = 0.f;
    unsigned long long bits = 0ull;
    for (int t = 0; t < LL; t++) {
        const float* eb = &g_evbase[(size_t)(b * LL + t) * NE];
        float* ob = &out_ev[(size_t)(b * LL + t) * NE];
        float bestv = -1e30f;
        int besti = 0;
#pragma unroll
        for (int e = 0; e < NE; e++) {
            float v = eb[e] + ctrg[e];
            ob[e] = v;
            if (v > bestv) { bestv = v; besti = e; }
        }
        g_emask[b * LL + t] = (besti > 0) ? 1 : 0;
        if (besti > 0) {
            int j = besti - 1;
            if (!((bits >> j) & 1ull)) {
                bits |= 1ull << j;
#pragma unroll
                for (int e = 0; e < NE; e++) ctrg[e] += g_WeGT[j * NE + e];
            }
        }
    }
}

// ---------------- kernel 7 (stage B): 8192 independent (b,pos) argument chains ----------------
__global__ void k_stageB(float* __restrict__ out_arg) {
    __shared__ unsigned char em[LL];
    int b = blockIdx.x;      // 64 blocks
    int pos = threadIdx.x;   // 128 threads
    em[pos] = g_emask[b * LL + pos];
    __syncthreads();

    float4 base[9], C[9];
    const float4* bp = (const float4*)&g_base36[(size_t)(b * LL + pos) * NA];
#pragma unroll
    for (int q = 0; q < 9; q++) { base[q] = bp[q]; C[q] = make_float4(0.f, 0.f, 0.f, 0.f); }
    unsigned long long bits = 0ull;

    for (int t = 0; t < LL; t++) {
        const float4* th = (const float4*)&g_thadd[(size_t)(b * LL + t) * NA];
        float4* op = (float4*)&out_arg[((size_t)(b * LL + t) * LL + pos) * NA];
        float bestv = -1e30f;
        int besti = 0;
#pragma unroll
        for (int q = 0; q < 9; q++) {
            float4 tv = __ldg(&th[q]);
            float4 o;
            o.x = base[q].x + C[q].x + tv.x;
            o.y = base[q].y + C[q].y + tv.y;
            o.z = base[q].z + C[q].z + tv.z;
            o.w = base[q].w + C[q].w + tv.w;
            op[q] = o;
            if (o.x > bestv) { bestv = o.x; besti = q * 4 + 0; }
            if (o.y > bestv) { bestv = o.y; besti = q * 4 + 1; }
            if (o.z > bestv) { bestv = o.z; besti = q * 4 + 2; }
            if (o.w > bestv) { bestv = o.w; besti = q * 4 + 3; }
        }
        if (em[t] && besti > 0) {
            int j = besti - 1;
            if (!((bits >> j) & 1ull)) {
                bits |= 1ull << j;
                const float4* wg = (const float4*)&g_WaGT[j * NA];
#pragma unroll
                for (int q = 0; q < 9; q++) {
                    float4 w = wg[q];
                    C[q].x += w.x; C[q].y += w.y; C[q].z += w.z; C[q].w += w.w;
                }
            }
        }
    }
}

// ---------------- launch ----------------
extern "C" void kernel_launch(void* const* d_in, const int* in_sizes, int n_in,
                              void* d_out, int out_size) {
    const int*   ids  = (const int*)  d_in[0];
    const float* emb  = (const float*)d_in[1];
    const float* Wihf = (const float*)d_in[2];
    const float* Whhf = (const float*)d_in[3];
    const float* bf   = (const float*)d_in[4];
    const float* Wihb = (const float*)d_in[5];
    const float* Whhb = (const float*)d_in[6];
    const float* bbv  = (const float*)d_in[7];
    const float* We   = (const float*)d_in[8];
    const float* be   = (const float*)d_in[9];
    const float* Wa   = (const float*)d_in[10];
    const float* ba   = (const float*)d_in[11];

    float* out_ev  = (float*)d_out;                       // [64,128,34]
    float* out_arg = out_ev + (size_t)BB * LL * NE;       // [64,128,128,36]

    cudaFuncSetAttribute(k_lstm_step, cudaFuncAttributeMaxDynamicSharedMemorySize, 90112);

    k_gather<<<LL * BB, 128>>>(ids, emb);
    k_prep<<<64, 256>>>(We, Wa);
    k_gemm1<<<dim3(32, 128), 256>>>(Wihf, Wihb, bf, bbv);
    for (int s = 0; s < LL; s++) {
        k_lstm_step<<<128, 256, 90112>>>(Whhf, Whhb, s);
    }
    k_gemm2<<<128, 256>>>(be, ba);
    k_stageA<<<1, 64>>>(out_ev);
    k_stageB<<<64, 128>>>(out_arg);
}

// round 3
// speedup vs baseline: 1.0734x; 1.0734x over previous
#include <cuda_runtime.h>
#include <math.h>
#include <stdint.h>

static constexpr int BB   = 64;
static constexpr int LL   = 128;
static constexpr int EMBD = 300;
static constexpr int HH   = 256;
static constexpr int NE   = 34;
static constexpr int NA   = 36;

// ---------------- scratch ----------------
__device__ float g_x   [LL * BB * EMBD];
__device__ float g_xg  [LL * BB * 2048];          // [t][b][dir*1024 + g*256 + u]
__device__ float g_hs2 [LL * 2 * BB * HH];        // [t][dir][b][u]
__device__ float g_evbase[BB * LL * NE];
__device__ float g_base36[BB * LL * NA];
__device__ float g_thadd [BB * LL * NA];
__device__ float g_Wcat [112 * 512];
__device__ float g_WeGT [33 * 34];
__device__ float g_WaGT [35 * 36];
__device__ unsigned char g_emask[BB * LL];
__device__ unsigned int g_bar;

// ---------------- f32x2 helpers ----------------
__device__ __forceinline__ uint64_t pk2(float x, float y) {
    uint64_t r; asm("mov.b64 %0,{%1,%2};" : "=l"(r) : "f"(x), "f"(y)); return r;
}
__device__ __forceinline__ uint64_t ffma2(uint64_t a, uint64_t b, uint64_t c) {
    uint64_t d; asm("fma.rn.f32x2 %0,%1,%2,%3;" : "=l"(d) : "l"(a), "l"(b), "l"(c)); return d;
}
__device__ __forceinline__ float2 up2(uint64_t v) {
    float2 r; asm("mov.b64 {%0,%1},%2;" : "=f"(r.x), "=f"(r.y) : "l"(v)); return r;
}

// ---------------- kernel 1: embedding gather ----------------
__global__ void k_gather(const int* __restrict__ ids, const float* __restrict__ emb) {
    int bx = blockIdx.x;          // t*64 + b
    int t = bx >> 6;
    int b = bx & 63;
    int id = ids[b * LL + t];
    const float4* src = (const float4*)(emb + (size_t)id * EMBD);
    float4* dst = (float4*)(g_x + (size_t)bx * EMBD);
    int i = threadIdx.x;
    if (i < 75) dst[i] = src[i];
}

// ---------------- kernel 2: pack decode weights + reset barrier ----------------
__global__ void k_prep(const float* __restrict__ We, const float* __restrict__ Wa) {
    if (blockIdx.x == 0 && threadIdx.x == 0) g_bar = 0u;
    int tid = blockIdx.x * blockDim.x + threadIdx.x;
    int stride = gridDim.x * blockDim.x;
    for (int i = tid; i < 112 * 512; i += stride) {
        int n = i >> 9, k = i & 511;
        float v = 0.f;
        if (n < 34)       v = We[n * 545 + k];
        else if (n < 70)  v = Wa[(n - 34) * 1059 + k];
        else if (n < 106) v = Wa[(n - 70) * 1059 + 512 + k];
        g_Wcat[i] = v;
    }
    for (int i = tid; i < 33 * 34; i += stride) {
        int j = i / 34, e = i % 34;
        g_WeGT[i] = We[e * 545 + 512 + j];
    }
    for (int i = tid; i < 35 * 36; i += stride) {
        int j = i / 36, e = i % 36;
        g_WaGT[i] = Wa[e * 1059 + 1024 + j];
    }
}

// ---------------- kernel 3: input GEMM (f32x2 inner) ----------------
__global__ void k_gemm1(const float* __restrict__ Wf, const float* __restrict__ Wb,
                        const float* __restrict__ bf, const float* __restrict__ bbv) {
    __shared__ float Ash[20][68];
    __shared__ float Bsh[20][68];
    int n0 = blockIdx.x * 64;
    int m0 = blockIdx.y * 64;
    int dir = n0 >> 10;
    int j0 = n0 & 1023;
    const float* W    = dir ? Wb  : Wf;
    const float* bias = dir ? bbv : bf;
    int tid = threadIdx.x;
    int tm = tid & 15, tn = tid >> 4;
    uint64_t acc[4][2];
#pragma unroll
    for (int i = 0; i < 4; i++) { acc[i][0] = 0ull; acc[i][1] = 0ull; }
    for (int kt = 0; kt < 15; kt++) {
        int k0 = kt * 20;
#pragma unroll
        for (int i = 0; i < 5; i++) {
            int idx = i * 256 + tid;
            int r = idx / 20, kk = idx % 20;
            Ash[kk][r] = g_x[(size_t)(m0 + r) * EMBD + k0 + kk];
            Bsh[kk][r] = W[(size_t)(j0 + r) * EMBD + k0 + kk];
        }
        __syncthreads();
#pragma unroll
        for (int kk = 0; kk < 20; kk++) {
            float4 a = *(float4*)&Ash[kk][tm * 4];
            float4 bv = *(float4*)&Bsh[kk][tn * 4];
            uint64_t b01 = pk2(bv.x, bv.y);
            uint64_t b23 = pk2(bv.z, bv.w);
            uint64_t a0 = pk2(a.x, a.x), a1 = pk2(a.y, a.y);
            uint64_t a2 = pk2(a.z, a.z), a3 = pk2(a.w, a.w);
            acc[0][0] = ffma2(a0, b01, acc[0][0]); acc[0][1] = ffma2(a0, b23, acc[0][1]);
            acc[1][0] = ffma2(a1, b01, acc[1][0]); acc[1][1] = ffma2(a1, b23, acc[1][1]);
            acc[2][0] = ffma2(a2, b01, acc[2][0]); acc[2][1] = ffma2(a2, b23, acc[2][1]);
            acc[3][0] = ffma2(a3, b01, acc[3][0]); acc[3][1] = ffma2(a3, b23, acc[3][1]);
        }
        __syncthreads();
    }
    float b0 = bias[j0 + tn * 4 + 0], b1 = bias[j0 + tn * 4 + 1];
    float b2 = bias[j0 + tn * 4 + 2], b3 = bias[j0 + tn * 4 + 3];
#pragma unroll
    for (int i = 0; i < 4; i++) {
        int m = m0 + tm * 4 + i;
        float2 p0 = up2(acc[i][0]);
        float2 p1 = up2(acc[i][1]);
        float4 o;
        o.x = p0.x + b0; o.y = p0.y + b1; o.z = p1.x + b2; o.w = p1.y + b3;
        *(float4*)&g_xg[(size_t)m * 2048 + n0 + tn * 4] = o;
    }
}

// ---------------- kernel 4: persistent LSTM over all 128 steps ----------------
// 128 blocks (dir = bx>>6, 4 units each), 256 threads, custom grid barrier.
__global__ void __launch_bounds__(256, 1)
k_lstm_all(const float* __restrict__ Whf, const float* __restrict__ Whb) {
    extern __shared__ float sm[];
    float* wsh = sm;                    // [k][16 rows]  4096 floats
    float* hsh = sm + 4096;             // [b][k] pad 260: 64*260 floats
    float* gsh = hsh + 64 * 260;        // [16 rows][64 b]
    int bx = blockIdx.x;
    int dir = bx >> 6;
    int u0 = (bx & 63) * 4;
    const float* W = dir ? Whb : Whf;
    int tid = threadIdx.x;

    // Load W once: row = g*4+uu  ->  W[(g*256 + u0+uu)*256 + k]
#pragma unroll
    for (int i = 0; i < 16; i++) {
        int idx = i * 256 + tid;
        int row = idx >> 8;
        int k = idx & 255;
        int g = row >> 2, uu = row & 3;
        wsh[k * 16 + row] = W[(size_t)(g * HH + u0 + uu) * HH + k];
    }

    int rg = tid >> 6;   // 0..3: gate index; computes rows rg*4..rg*4+3
    int b  = tid & 63;
    float c_reg = 0.f;   // cell state for (b, u0 + rg) — fixed thread mapping
    unsigned goal = 0;

    for (int s = 0; s < LL; s++) {
        int t = dir ? (LL - 1 - s) : s;

        uint64_t a01 = 0ull, a23 = 0ull;
        if (s > 0) {
            const float* hrow = &hsh[b * 260];
#pragma unroll 8
            for (int k4 = 0; k4 < 64; k4++) {
                float4 h4 = *(const float4*)&hrow[k4 * 4];
#pragma unroll
                for (int i = 0; i < 4; i++) {
                    float4 w = *(const float4*)&wsh[(k4 * 4 + i) * 16 + rg * 4];
                    float hv = (i == 0) ? h4.x : (i == 1) ? h4.y : (i == 2) ? h4.z : h4.w;
                    uint64_t hd  = pk2(hv, hv);
                    uint64_t w01 = pk2(w.x, w.y);
                    uint64_t w23 = pk2(w.z, w.w);
                    a01 = ffma2(w01, hd, a01);
                    a23 = ffma2(w23, hd, a23);
                }
            }
        }
        float2 v01 = up2(a01), v23 = up2(a23);
        gsh[(rg * 4 + 0) * 64 + b] = v01.x;
        gsh[(rg * 4 + 1) * 64 + b] = v01.y;
        gsh[(rg * 4 + 2) * 64 + b] = v23.x;
        gsh[(rg * 4 + 3) * 64 + b] = v23.y;
        __syncthreads();

        // final phase: thread (uu = rg, b) handles unit u0+rg for batch b
        {
            int uu = rg;
            int u = u0 + uu;
            size_t xb = (size_t)(t * BB + b) * 2048 + dir * 1024 + u;
            float gi = gsh[(0 * 4 + uu) * 64 + b] + g_xg[xb + 0 * HH];
            float gf = gsh[(1 * 4 + uu) * 64 + b] + g_xg[xb + 1 * HH];
            float gg = gsh[(2 * 4 + uu) * 64 + b] + g_xg[xb + 2 * HH];
            float go = gsh[(3 * 4 + uu) * 64 + b] + g_xg[xb + 3 * HH];
            float si = 1.f / (1.f + expf(-gi));
            float sf = 1.f / (1.f + expf(-gf));
            float so = 1.f / (1.f + expf(-go));
            float c = (s > 0) ? c_reg : 0.f;
            c = sf * c + si * tanhf(gg);
            c_reg = c;
            float h = so * tanhf(c);
            g_hs2[((size_t)(t * 2 + dir) * BB + b) * HH + u] = h;
        }
        __threadfence();
        __syncthreads();
        if (tid == 0) {
            atomicAdd(&g_bar, 1u);
            goal += 128u;
            volatile unsigned* vb = &g_bar;
            while (*vb < goal) { __nanosleep(32); }
        }
        __syncthreads();

        if (s < LL - 1) {
            // load h(t) (this step's output across all blocks of this dir) into hsh[b][k]
            size_t base = (size_t)(t * 2 + dir) * BB * HH;
#pragma unroll
            for (int i = 0; i < 16; i++) {
                int idx4 = i * 256 + tid;
                int bb = idx4 >> 6;
                int k4 = idx4 & 63;
                float4 v = *(const float4*)&g_hs2[base + (size_t)idx4 * 4];
                *(float4*)&hsh[bb * 260 + k4 * 4] = v;
            }
            __syncthreads();
        }
    }
}

// ---------------- kernel 5: projection GEMM  hs[8192,512] @ Wcat^T ----------------
__global__ void k_gemm2(const float* __restrict__ be, const float* __restrict__ ba) {
    __shared__ float Ash[16][68];
    __shared__ float Bsh[16][116];
    int m0 = blockIdx.x * 64;
    int bB = m0 >> 7;            // batch for this tile
    int t0 = m0 & 127;           // t offset
    int tid = threadIdx.x;
    int tm = tid & 15, tn = tid >> 4;
    float acc[4][7] = {};
    for (int kt = 0; kt < 32; kt++) {
        int k0 = kt * 16;
#pragma unroll
        for (int i = 0; i < 4; i++) {
            int idx = i * 256 + tid;
            int mm = idx >> 4, kk = idx & 15;
            int k = k0 + kk;
            int dir = k >> 8, u = k & 255;
            Ash[kk][mm] = g_hs2[((size_t)((t0 + mm) * 2 + dir) * BB + bB) * HH + u];
        }
#pragma unroll
        for (int i = 0; i < 7; i++) {
            int idx = i * 256 + tid;
            int nn = idx >> 4, kk = idx & 15;
            Bsh[kk][nn] = g_Wcat[(size_t)nn * 512 + k0 + kk];
        }
        __syncthreads();
#pragma unroll
        for (int kk = 0; kk < 16; kk++) {
            float4 a = *(float4*)&Ash[kk][tm * 4];
#pragma unroll
            for (int j = 0; j < 7; j++) {
                float bv = Bsh[kk][tn * 7 + j];
                acc[0][j] += a.x * bv;
                acc[1][j] += a.y * bv;
                acc[2][j] += a.z * bv;
                acc[3][j] += a.w * bv;
            }
        }
        __syncthreads();
    }
#pragma unroll
    for (int i = 0; i < 4; i++) {
        int m = m0 + tm * 4 + i;
#pragma unroll
        for (int j = 0; j < 7; j++) {
            int n = tn * 7 + j;
            float v = acc[i][j];
            if (n < 34)       g_evbase[(size_t)m * NE + n]        = v + be[n];
            else if (n < 70)  g_base36[(size_t)m * NA + (n - 34)] = v + ba[n - 34];
            else if (n < 106) g_thadd [(size_t)m * NA + (n - 70)] = v;
        }
    }
}

// ---------------- kernel 6: event chains ----------------
__global__ void k_stageA(float* __restrict__ out_ev) {
    int b = threadIdx.x;
    float ctrg[NE];
#pragma unroll
    for (int e = 0; e < NE; e++) ctrg[e] = 0.f;
    unsigned long long bits = 0ull;
    for (int t = 0; t < LL; t++) {
        const float* eb = &g_evbase[(size_t)(b * LL + t) * NE];
        float* ob = &out_ev[(size_t)(b * LL + t) * NE];
        float bestv = -1e30f;
        int besti = 0;
#pragma unroll
        for (int e = 0; e < NE; e++) {
            float v = eb[e] + ctrg[e];
            ob[e] = v;
            if (v > bestv) { bestv = v; besti = e; }
        }
        g_emask[b * LL + t] = (besti > 0) ? 1 : 0;
        if (besti > 0) {
            int j = besti - 1;
            if (!((bits >> j) & 1ull)) {
                bits |= 1ull << j;
#pragma unroll
                for (int e = 0; e < NE; e++) ctrg[e] += g_WeGT[j * NE + e];
            }
        }
    }
}

// ---------------- kernel 7: argument chains, 4 threads per (b,pos) ----------------
__global__ void k_stageB(float* __restrict__ out_arg) {
    __shared__ unsigned char em[LL];
    __shared__ float was[35 * 36];
    int b = blockIdx.x;
    int tid = threadIdx.x;      // 512
    int pos = tid >> 2;
    int q = tid & 3;            // handles floats [q*9, q*9+9)
    if (tid < LL) em[tid] = g_emask[b * LL + tid];
    for (int i = tid; i < 35 * 36; i += 512) was[i] = g_WaGT[i];
    __syncthreads();

    float base[9], C[9];
    const float* bp = &g_base36[(size_t)(b * LL + pos) * NA + q * 9];
#pragma unroll
    for (int i = 0; i < 9; i++) { base[i] = bp[i]; C[i] = 0.f; }
    unsigned long long bits = 0ull;

    for (int t = 0; t < LL; t++) {
        const float* th = &g_thadd[(size_t)(b * LL + t) * NA + q * 9];
        float* op = &out_arg[((size_t)(b * LL + t) * LL + pos) * NA + q * 9];
        float o[9];
        float bestv = -1e30f;
        int besti = 1000;
#pragma unroll
        for (int i = 0; i < 9; i++) {
            o[i] = base[i] + C[i] + __ldg(&th[i]);
            if (o[i] > bestv) { bestv = o[i]; besti = q * 9 + i; }
        }
        // reduce across the 4 lanes of this chain (prefer lower index on ties)
#pragma unroll
        for (int off = 1; off < 4; off <<= 1) {
            float ov = __shfl_xor_sync(0xffffffffu, bestv, off, 4);
            int   oi = __shfl_xor_sync(0xffffffffu, besti, off, 4);
            if (ov > bestv || (ov == bestv && oi < besti)) { bestv = ov; besti = oi; }
        }
#pragma unroll
        for (int i = 0; i < 9; i++) op[i] = o[i];
        if (em[t] && besti > 0) {
            int j = besti - 1;
            if (!((bits >> j) & 1ull)) {
                bits |= 1ull << j;
                const float* wg = &was[j * NA + q * 9];
#pragma unroll
                for (int i = 0; i < 9; i++) C[i] += wg[i];
            }
        }
    }
}

// ---------------- launch ----------------
extern "C" void kernel_launch(void* const* d_in, const int* in_sizes, int n_in,
                              void* d_out, int out_size) {
    const int*   ids  = (const int*)  d_in[0];
    const float* emb  = (const float*)d_in[1];
    const float* Wihf = (const float*)d_in[2];
    const float* Whhf = (const float*)d_in[3];
    const float* bf   = (const float*)d_in[4];
    const float* Wihb = (const float*)d_in[5];
    const float* Whhb = (const float*)d_in[6];
    const float* bbv  = (const float*)d_in[7];
    const float* We   = (const float*)d_in[8];
    const float* be   = (const float*)d_in[9];
    const float* Wa   = (const float*)d_in[10];
    const float* ba   = (const float*)d_in[11];

    float* out_ev  = (float*)d_out;
    float* out_arg = out_ev + (size_t)BB * LL * NE;

    const int lstm_smem = (4096 + 64 * 260 + 16 * 64) * 4;  // 87040 B
    cudaFuncSetAttribute(k_lstm_all, cudaFuncAttributeMaxDynamicSharedMemorySize, lstm_smem);

    k_gather<<<LL * BB, 128>>>(ids, emb);
    k_prep<<<64, 256>>>(We, Wa);
    k_gemm1<<<dim3(32, 128), 256>>>(Wihf, Wihb, bf, bbv);
    k_lstm_all<<<128, 256, lstm_smem>>>(Whhf, Whhb);
    k_gemm2<<<128, 256>>>(be, ba);
    k_stageA<<<1, 64>>>(out_ev);
    k_stageB<<<64, 512>>>(out_arg);
}

// round 4
// speedup vs baseline: 1.1882x; 1.1069x over previous
#include <cuda_runtime.h>
#include <math.h>
#include <stdint.h>

static constexpr int BB   = 64;
static constexpr int LL   = 128;
static constexpr int EMBD = 300;
static constexpr int HH   = 256;
static constexpr int NE   = 34;
static constexpr int NA   = 36;

// ---------------- scratch ----------------
__device__ float g_x   [LL * BB * EMBD];          // [m=t*64+b][e]
__device__ float g_xg  [LL * BB * 2048];          // [m][dir*1024 + g*256 + u]
__device__ float g_hsT [LL * 2 * HH * BB];        // [t][dir][u][b]
__device__ float g_evbase[LL * BB * NE];          // [m=t*64+b][34]
__device__ float g_base36[LL * BB * NA];          // [m=pos*64+b][36]
__device__ float g_thadd [LL * BB * NA];          // [m=t*64+b][36]
__device__ float g_Wcat [112 * 512];
__device__ float g_WeGT [33 * 34];
__device__ float g_WaGT [35 * 36];
__device__ unsigned char g_emask[BB * LL];
__device__ unsigned int g_barD[2];

// ---------------- f32x2 helpers ----------------
__device__ __forceinline__ uint64_t pk2(float x, float y) {
    uint64_t r; asm("mov.b64 %0,{%1,%2};" : "=l"(r) : "f"(x), "f"(y)); return r;
}
__device__ __forceinline__ uint64_t ffma2(uint64_t a, uint64_t b, uint64_t c) {
    uint64_t d; asm("fma.rn.f32x2 %0,%1,%2,%3;" : "=l"(d) : "l"(a), "l"(b), "l"(c)); return d;
}
__device__ __forceinline__ float2 up2(uint64_t v) {
    float2 r; asm("mov.b64 {%0,%1},%2;" : "=f"(r.x), "=f"(r.y) : "l"(v)); return r;
}

// ---------------- kernel 1: embedding gather ----------------
__global__ void k_gather(const int* __restrict__ ids, const float* __restrict__ emb) {
    int bx = blockIdx.x;          // m = t*64 + b
    int t = bx >> 6;
    int b = bx & 63;
    int id = ids[b * LL + t];
    const float4* src = (const float4*)(emb + (size_t)id * EMBD);
    float4* dst = (float4*)(g_x + (size_t)bx * EMBD);
    int i = threadIdx.x;
    if (i < 75) dst[i] = src[i];
}

// ---------------- kernel 2: pack decode weights + reset barriers ----------------
__global__ void k_prep(const float* __restrict__ We, const float* __restrict__ Wa) {
    if (blockIdx.x == 0 && threadIdx.x == 0) { g_barD[0] = 0u; g_barD[1] = 0u; }
    int tid = blockIdx.x * blockDim.x + threadIdx.x;
    int stride = gridDim.x * blockDim.x;
    for (int i = tid; i < 112 * 512; i += stride) {
        int n = i >> 9, k = i & 511;
        float v = 0.f;
        if (n < 34)       v = We[n * 545 + k];
        else if (n < 70)  v = Wa[(n - 34) * 1059 + k];
        else if (n < 106) v = Wa[(n - 70) * 1059 + 512 + k];
        g_Wcat[i] = v;
    }
    for (int i = tid; i < 33 * 34; i += stride) {
        int j = i / 34, e = i % 34;
        g_WeGT[i] = We[e * 545 + 512 + j];
    }
    for (int i = tid; i < 35 * 36; i += stride) {
        int j = i / 36, e = i % 36;
        g_WaGT[i] = Wa[e * 1059 + 1024 + j];
    }
}

// ---------------- kernel 3: input GEMM (dup-A f32x2) ----------------
// M=8192, N=2048, K=300. 64x64 tiles.
__global__ void k_gemm1(const float* __restrict__ Wf, const float* __restrict__ Wb,
                        const float* __restrict__ bf, const float* __restrict__ bbv) {
    __shared__ uint64_t Ashd[20 * 64];   // [kk][r] duplicated A
    __shared__ float    Bsh[20][68];
    int n0 = blockIdx.x * 64;
    int m0 = blockIdx.y * 64;
    int dir = n0 >> 10;
    int j0 = n0 & 1023;
    const float* W    = dir ? Wb  : Wf;
    const float* bias = dir ? bbv : bf;
    int tid = threadIdx.x;
    int tm = tid & 15, tn = tid >> 4;
    uint64_t acc[4][2];
#pragma unroll
    for (int i = 0; i < 4; i++) { acc[i][0] = 0ull; acc[i][1] = 0ull; }
    for (int kt = 0; kt < 15; kt++) {
        int k0 = kt * 20;
#pragma unroll
        for (int i = 0; i < 5; i++) {
            int idx = i * 256 + tid;     // 0..1279
            int r = idx / 20, kk = idx % 20;
            float av = g_x[(size_t)(m0 + r) * EMBD + k0 + kk];
            Ashd[kk * 64 + r] = pk2(av, av);
            Bsh[kk][r] = W[(size_t)(j0 + r) * EMBD + k0 + kk];
        }
        __syncthreads();
#pragma unroll
        for (int kk = 0; kk < 20; kk++) {
            ulonglong2 a01 = *(const ulonglong2*)(Ashd + kk * 64 + tm * 4);
            ulonglong2 a23 = *(const ulonglong2*)(Ashd + kk * 64 + tm * 4 + 2);
            ulonglong2 bq  = *(const ulonglong2*)&Bsh[kk][tn * 4];
            acc[0][0] = ffma2(a01.x, bq.x, acc[0][0]); acc[0][1] = ffma2(a01.x, bq.y, acc[0][1]);
            acc[1][0] = ffma2(a01.y, bq.x, acc[1][0]); acc[1][1] = ffma2(a01.y, bq.y, acc[1][1]);
            acc[2][0] = ffma2(a23.x, bq.x, acc[2][0]); acc[2][1] = ffma2(a23.x, bq.y, acc[2][1]);
            acc[3][0] = ffma2(a23.y, bq.x, acc[3][0]); acc[3][1] = ffma2(a23.y, bq.y, acc[3][1]);
        }
        __syncthreads();
    }
    float b0 = bias[j0 + tn * 4 + 0], b1 = bias[j0 + tn * 4 + 1];
    float b2 = bias[j0 + tn * 4 + 2], b3 = bias[j0 + tn * 4 + 3];
#pragma unroll
    for (int i = 0; i < 4; i++) {
        int m = m0 + tm * 4 + i;
        float2 p0 = up2(acc[i][0]);
        float2 p1 = up2(acc[i][1]);
        float4 o;
        o.x = p0.x + b0; o.y = p0.y + b1; o.z = p1.x + b2; o.w = p1.y + b3;
        *(float4*)&g_xg[(size_t)m * 2048 + n0 + tn * 4] = o;
    }
}

// ---------------- kernel 4: persistent LSTM ----------------
// 128 blocks (dir = bx>>6, 4 units = 16 gate-rows), 256 threads.
// MAC thread = (kc: k-chunk of 64, rg: gate, bg: 4-batch group) -> 4 rows x 4 b f32x2 tile.
__global__ void __launch_bounds__(256, 1)
k_lstm_all(const float* __restrict__ Whf, const float* __restrict__ Whb) {
    extern __shared__ float sm[];
    uint64_t* wdup = (uint64_t*)sm;      // [k*16 + row] u64  (32768 B)
    float* hsm = sm + 8192;              // [k][b]  256*64    (65536 B)
    float* red = hsm + 16384;            // [kc][row][b] 4*16*64 (16384 B)

    int bx = blockIdx.x;
    int dir = bx >> 6;
    int u0 = (bx & 63) * 4;
    const float* W = dir ? Whb : Whf;
    int tid = threadIdx.x;

    // fill wdup once: row = g*4+uu, value = dup(W[(g*256 + u0+uu)*256 + k])
#pragma unroll
    for (int i = 0; i < 16; i++) {
        int idx = i * 256 + tid;         // = k*16 + row
        int row = idx & 15;
        int k = idx >> 4;
        int g = row >> 2, uu = row & 3;
        float w = W[(size_t)(g * HH + u0 + uu) * HH + k];
        wdup[idx] = pk2(w, w);
    }

    int kc = tid >> 6;
    int rg = (tid >> 4) & 3;
    int bg = tid & 15;
    int fu = tid >> 6;        // final-phase unit
    int fb = tid & 63;        // final-phase batch
    float c_reg = 0.f;
    unsigned goal = 0;
    unsigned int* ctr = &g_barD[dir];

    const uint64_t* wp0 = wdup + (size_t)(kc * 64) * 16 + rg * 4;
    const float*    hp0 = hsm + (size_t)(kc * 64) * 64 + bg * 4;

    for (int s = 0; s < LL; s++) {
        int t = dir ? (LL - 1 - s) : s;

        uint64_t acc[4][2];
#pragma unroll
        for (int i = 0; i < 4; i++) { acc[i][0] = 0ull; acc[i][1] = 0ull; }
        if (s > 0) {
            const uint64_t* wp = wp0;
            const float* hp = hp0;
#pragma unroll 4
            for (int kk = 0; kk < 64; kk++) {
                ulonglong2 wa = *(const ulonglong2*)(wp);
                ulonglong2 wb = *(const ulonglong2*)(wp + 2);
                ulonglong2 hh = *(const ulonglong2*)(hp);
                acc[0][0] = ffma2(wa.x, hh.x, acc[0][0]);
                acc[0][1] = ffma2(wa.x, hh.y, acc[0][1]);
                acc[1][0] = ffma2(wa.y, hh.x, acc[1][0]);
                acc[1][1] = ffma2(wa.y, hh.y, acc[1][1]);
                acc[2][0] = ffma2(wb.x, hh.x, acc[2][0]);
                acc[2][1] = ffma2(wb.x, hh.y, acc[2][1]);
                acc[3][0] = ffma2(wb.y, hh.x, acc[3][0]);
                acc[3][1] = ffma2(wb.y, hh.y, acc[3][1]);
                wp += 16;
                hp += 64;
            }
        }
        // stage partials: red[kc][rg*4 + i][bg*4..+3]
        {
            float* rp = red + (size_t)(kc * 16 + rg * 4) * 64 + bg * 4;
#pragma unroll
            for (int i = 0; i < 4; i++) {
                float2 p0 = up2(acc[i][0]);
                float2 p1 = up2(acc[i][1]);
                *(float4*)(rp + i * 64) = make_float4(p0.x, p0.y, p1.x, p1.y);
            }
        }
        __syncthreads();

        // final: thread (fu, fb) -> unit u0+fu, batch fb
        {
            float gate[4];
#pragma unroll
            for (int g = 0; g < 4; g++) {
                float ssum = 0.f;
#pragma unroll
                for (int kcx = 0; kcx < 4; kcx++)
                    ssum += red[(size_t)(kcx * 16 + g * 4 + fu) * 64 + fb];
                gate[g] = ssum + g_xg[(size_t)(t * 64 + fb) * 2048 + dir * 1024 + g * 256 + u0 + fu];
            }
            float si = 1.f / (1.f + expf(-gate[0]));
            float sf = 1.f / (1.f + expf(-gate[1]));
            float so = 1.f / (1.f + expf(-gate[3]));
            float c = (s > 0) ? c_reg : 0.f;
            c = sf * c + si * tanhf(gate[2]);
            c_reg = c;
            float h = so * tanhf(c);
            g_hsT[((size_t)(t * 2 + dir) * HH + u0 + fu) * 64 + fb] = h;
        }
        __syncthreads();

        if (s < LL - 1) {
            // per-dir grid barrier: release/acquire
            if (tid == 0) {
                asm volatile("red.release.gpu.global.add.u32 [%0], %1;" :: "l"(ctr), "r"(1u) : "memory");
                goal += 64u;
                unsigned v;
                while (1) {
                    asm volatile("ld.acquire.gpu.global.u32 %0, [%1];" : "=r"(v) : "l"(ctr) : "memory");
                    if (v >= goal) break;
                    __nanosleep(64);
                }
            }
            __syncthreads();
            // refill hsm with h(t) of this dir: straight coalesced copy
            const float4* src = (const float4*)(g_hsT + (size_t)(t * 2 + dir) * HH * 64);
            float4* dst = (float4*)hsm;
#pragma unroll
            for (int i = 0; i < 16; i++) dst[i * 256 + tid] = src[i * 256 + tid];
            __syncthreads();
        }
    }
}

// ---------------- kernel 5: projection GEMM  hs[8192,512] @ Wcat^T ----------------
// block = one t; m = t*64 + b; A slab g_hsT[t] is [k=512][b=64], coalesced.
__global__ void k_gemm2(const float* __restrict__ be, const float* __restrict__ ba) {
    __shared__ float Ash[16][64];
    __shared__ float Bsh[16][116];
    int t = blockIdx.x;
    const float* slabA = g_hsT + (size_t)t * 512 * 64;
    int tid = threadIdx.x;
    int tm = tid & 15, tn = tid >> 4;
    float acc[4][7] = {};
    for (int kt = 0; kt < 32; kt++) {
        int k0 = kt * 16;
        {
            int kk = tid >> 4, b4 = (tid & 15) * 4;
            *(float4*)&Ash[kk][b4] = *(const float4*)(slabA + (size_t)(k0 + kk) * 64 + b4);
        }
#pragma unroll
        for (int i = 0; i < 7; i++) {
            int idx = i * 256 + tid;
            int nn = idx >> 4, kk = idx & 15;
            Bsh[kk][nn] = g_Wcat[(size_t)nn * 512 + k0 + kk];
        }
        __syncthreads();
#pragma unroll
        for (int kk = 0; kk < 16; kk++) {
            float4 a = *(float4*)&Ash[kk][tm * 4];
#pragma unroll
            for (int j = 0; j < 7; j++) {
                float bv = Bsh[kk][tn * 7 + j];
                acc[0][j] += a.x * bv;
                acc[1][j] += a.y * bv;
                acc[2][j] += a.z * bv;
                acc[3][j] += a.w * bv;
            }
        }
        __syncthreads();
    }
#pragma unroll
    for (int i = 0; i < 4; i++) {
        int m = t * 64 + tm * 4 + i;
#pragma unroll
        for (int j = 0; j < 7; j++) {
            int n = tn * 7 + j;
            float v = acc[i][j];
            if (n < 34)       g_evbase[(size_t)m * NE + n]        = v + be[n];
            else if (n < 70)  g_base36[(size_t)m * NA + (n - 34)] = v + ba[n - 34];
            else if (n < 106) g_thadd [(size_t)m * NA + (n - 70)] = v;
        }
    }
}

// ---------------- kernel 6: event chains (4 lanes per batch) ----------------
__global__ void k_stageA(float* __restrict__ out_ev) {
    __shared__ float was[33 * 34];
    int tid = threadIdx.x;    // 256
    int b = tid >> 2, q = tid & 3;
    for (int i = tid; i < 33 * 34; i += 256) was[i] = g_WeGT[i];
    __syncthreads();
    int n0 = q * 9;
    int cnt = (q == 3) ? 7 : 9;
    float ctrg[9];
#pragma unroll
    for (int i = 0; i < 9; i++) ctrg[i] = 0.f;
    unsigned long long bits = 0ull;
    for (int t = 0; t < LL; t++) {
        const float* eb = &g_evbase[(size_t)(t * 64 + b) * NE + n0];
        float o[9];
        float bestv = -1e30f;
        int besti = 1000;
#pragma unroll
        for (int i = 0; i < 9; i++) {
            if (i < cnt) {
                o[i] = eb[i] + ctrg[i];
                if (o[i] > bestv) { bestv = o[i]; besti = n0 + i; }
            }
        }
#pragma unroll
        for (int off = 1; off < 4; off <<= 1) {
            float ov = __shfl_xor_sync(0xffffffffu, bestv, off, 4);
            int   oi = __shfl_xor_sync(0xffffffffu, besti, off, 4);
            if (ov > bestv || (ov == bestv && oi < besti)) { bestv = ov; besti = oi; }
        }
        float* ob = &out_ev[((size_t)b * LL + t) * NE + n0];
#pragma unroll
        for (int i = 0; i < 9; i++) if (i < cnt) ob[i] = o[i];
        if (q == 0) g_emask[b * LL + t] = (besti > 0) ? 1 : 0;
        if (besti > 0) {
            int j = besti - 1;
            if (!((bits >> j) & 1ull)) {
                bits |= 1ull << j;
#pragma unroll
                for (int i = 0; i < 9; i++) if (i < cnt) ctrg[i] += was[j * NE + n0 + i];
            }
        }
    }
}

// ---------------- kernel 7: argument chains, staged coalesced output ----------------
__global__ void k_stageB(float* __restrict__ out_arg) {
    __shared__ float was[35 * 36];
    __shared__ unsigned char em[LL];
    __shared__ float sbuf[64 * 36];
    int bx = blockIdx.x;          // 128 blocks
    int b = bx >> 1, ph = bx & 1;
    int tid = threadIdx.x;        // 256
    int p = tid >> 2;
    int pos = ph * 64 + p;
    int q = tid & 3;
    int n0 = q * 9;
    if (tid < LL) em[tid] = g_emask[b * LL + tid];
    for (int i = tid; i < 35 * 36; i += 256) was[i] = g_WaGT[i];
    __syncthreads();

    float base[9], C[9];
    const float* bp = &g_base36[(size_t)(pos * 64 + b) * NA + n0];
#pragma unroll
    for (int i = 0; i < 9; i++) { base[i] = bp[i]; C[i] = 0.f; }
    unsigned long long bits = 0ull;

    for (int t = 0; t < LL; t++) {
        const float* th = &g_thadd[(size_t)(t * 64 + b) * NA + n0];
        float o[9];
        float bestv = -1e30f;
        int besti = 1000;
#pragma unroll
        for (int i = 0; i < 9; i++) {
            o[i] = base[i] + C[i] + th[i];
            if (o[i] > bestv) { bestv = o[i]; besti = n0 + i; }
        }
#pragma unroll
        for (int off = 1; off < 4; off <<= 1) {
            float ov = __shfl_xor_sync(0xffffffffu, bestv, off, 4);
            int   oi = __shfl_xor_sync(0xffffffffu, besti, off, 4);
            if (ov > bestv || (ov == bestv && oi < besti)) { bestv = ov; besti = oi; }
        }
        float* sb = &sbuf[p * 36 + n0];
#pragma unroll
        for (int i = 0; i < 9; i++) sb[i] = o[i];
        if (em[t] && besti > 0) {
            int j = besti - 1;
            if (!((bits >> j) & 1ull)) {
                bits |= 1ull << j;
#pragma unroll
                for (int i = 0; i < 9; i++) C[i] += was[j * NA + n0 + i];
            }
        }
        __syncthreads();
        const float4* sb4 = (const float4*)sbuf;
        float4* og = (float4*)(out_arg + ((size_t)(b * LL + t) * LL + ph * 64) * NA);
#pragma unroll
        for (int i2 = tid; i2 < 576; i2 += 256) og[i2] = sb4[i2];
        __syncthreads();
    }
}

// ---------------- launch ----------------
extern "C" void kernel_launch(void* const* d_in, const int* in_sizes, int n_in,
                              void* d_out, int out_size) {
    const int*   ids  = (const int*)  d_in[0];
    const float* emb  = (const float*)d_in[1];
    const float* Wihf = (const float*)d_in[2];
    const float* Whhf = (const float*)d_in[3];
    const float* bf   = (const float*)d_in[4];
    const float* Wihb = (const float*)d_in[5];
    const float* Whhb = (const float*)d_in[6];
    const float* bbv  = (const float*)d_in[7];
    const float* We   = (const float*)d_in[8];
    const float* be   = (const float*)d_in[9];
    const float* Wa   = (const float*)d_in[10];
    const float* ba   = (const float*)d_in[11];

    float* out_ev  = (float*)d_out;
    float* out_arg = out_ev + (size_t)BB * LL * NE;

    const int lstm_smem = 32768 + 65536 + 16384;   // 114688 B
    cudaFuncSetAttribute(k_lstm_all, cudaFuncAttributeMaxDynamicSharedMemorySize, lstm_smem);

    k_gather<<<LL * BB, 128>>>(ids, emb);
    k_prep<<<64, 256>>>(We, Wa);
    k_gemm1<<<dim3(32, 128), 256>>>(Wihf, Wihb, bf, bbv);
    k_lstm_all<<<128, 256, lstm_smem>>>(Whhf, Whhb);
    k_gemm2<<<128, 256>>>(be, ba);
    k_stageA<<<1, 256>>>(out_ev);
    k_stageB<<<128, 256>>>(out_arg);
}

// round 5
// speedup vs baseline: 1.5939x; 1.3415x over previous
#include <cuda_runtime.h>
#include <math.h>
#include <stdint.h>

static constexpr int BB   = 64;
static constexpr int LL   = 128;
static constexpr int EMBD = 300;
static constexpr int HH   = 256;
static constexpr int NE   = 34;
static constexpr int NA   = 36;

// ---------------- scratch ----------------
__device__ float g_xT  [300 * 8192];              // [e][m=t*64+b]
__device__ float g_WT  [2 * 300 * 1024];          // [dir][k][row]
__device__ float g_xg  [LL * 2 * 4 * HH * BB];    // [t][dir][g][u][b]
__device__ float g_hsT [LL * 2 * HH * BB];        // [t][dir][u][b]
__device__ float g_evbase[LL * BB * NE];          // [t*64+b][34]
__device__ float g_base36[LL * BB * NA];          // [pos*64+b][36]
__device__ float g_thadd [LL * BB * NA];          // [t*64+b][36]
__device__ float g_Wcat [112 * 512];
__device__ float g_WeGT [33 * 34];
__device__ float g_WaGT [35 * 36];
__device__ unsigned char g_emask[BB * LL];
__device__ unsigned int g_barD[2];

// ---------------- f32x2 helpers ----------------
__device__ __forceinline__ uint64_t pk2(float x, float y) {
    uint64_t r; asm("mov.b64 %0,{%1,%2};" : "=l"(r) : "f"(x), "f"(y)); return r;
}
__device__ __forceinline__ uint64_t ffma2(uint64_t a, uint64_t b, uint64_t c) {
    uint64_t d; asm("fma.rn.f32x2 %0,%1,%2,%3;" : "=l"(d) : "l"(a), "l"(b), "l"(c)); return d;
}
__device__ __forceinline__ uint64_t addx2(uint64_t a, uint64_t b) {
    uint64_t d; asm("add.rn.f32x2 %0,%1,%2;" : "=l"(d) : "l"(a), "l"(b)); return d;
}
__device__ __forceinline__ float2 up2(uint64_t v) {
    float2 r; asm("mov.b64 {%0,%1},%2;" : "=f"(r.x), "=f"(r.y) : "l"(v)); return r;
}

// ---------------- kernel 1: embedding gather (transposed out) ----------------
__global__ void k_gather(const int* __restrict__ ids, const float* __restrict__ emb) {
    int t = blockIdx.x;               // 128 blocks, 256 threads
    int tid = threadIdx.x;
    int b = tid >> 2, q = tid & 3;
    int id = ids[b * LL + t];
    const float4* src = (const float4*)(emb + (size_t)id * EMBD);
#pragma unroll
    for (int j = 0; j < 19; j++) {
        int e4 = q + j * 4;
        if (e4 < 75) {
            float4 v = src[e4];
            int e = e4 * 4;
            size_t base = (size_t)e * 8192 + t * 64 + b;
            g_xT[base]          = v.x;
            g_xT[base + 8192]   = v.y;
            g_xT[base + 16384]  = v.z;
            g_xT[base + 24576]  = v.w;
        }
    }
}

// ---------------- kernel 1b: transpose W_ih (both dirs) ----------------
__global__ void k_transW(const float* __restrict__ Wf, const float* __restrict__ Wb) {
    __shared__ float ts[32][33];
    const float* W = blockIdx.z ? Wb : Wf;
    float* out = g_WT + (size_t)blockIdx.z * 300 * 1024;
    int n0 = blockIdx.x * 32, k0 = blockIdx.y * 32;
    int tx = threadIdx.x, ty = threadIdx.y;   // 32 x 8
#pragma unroll
    for (int r = 0; r < 4; r++) {
        int row = ty + r * 8;
        int k = k0 + tx;
        if (k < 300) ts[row][tx] = W[(size_t)(n0 + row) * 300 + k];
    }
    __syncthreads();
#pragma unroll
    for (int r = 0; r < 4; r++) {
        int row = ty + r * 8;
        int k = k0 + row;
        if (k < 300) out[(size_t)k * 1024 + n0 + tx] = ts[tx][row];
    }
}

// ---------------- kernel 2: pack decode weights + reset barriers ----------------
__global__ void k_prep(const float* __restrict__ We, const float* __restrict__ Wa) {
    if (blockIdx.x == 0 && threadIdx.x == 0) { g_barD[0] = 0u; g_barD[1] = 0u; }
    int tid = blockIdx.x * blockDim.x + threadIdx.x;
    int stride = gridDim.x * blockDim.x;
    for (int i = tid; i < 112 * 512; i += stride) {
        int n = i >> 9, k = i & 511;
        float v = 0.f;
        if (n < 34)       v = We[n * 545 + k];
        else if (n < 70)  v = Wa[(n - 34) * 1059 + k];
        else if (n < 106) v = Wa[(n - 70) * 1059 + 512 + k];
        g_Wcat[i] = v;
    }
    for (int i = tid; i < 33 * 34; i += stride) {
        int j = i / 34, e = i % 34;
        g_WeGT[i] = We[e * 545 + 512 + j];
    }
    for (int i = tid; i < 35 * 36; i += stride) {
        int j = i / 36, e = i % 36;
        g_WaGT[i] = Wa[e * 1059 + 1024 + j];
    }
}

// ---------------- kernel 3: input GEMM, 128x128 tiles, 8x8/thread ----------------
__global__ void k_gemm1(const float* __restrict__ bf, const float* __restrict__ bbv) {
    __shared__ float Xs[20 * 128];
    __shared__ float Ws[20 * 128];
    int nb = blockIdx.x;              // 0..15
    int mb = blockIdx.y;              // 0..63
    int dir = nb >> 3;
    int j0 = (nb & 7) * 128;
    int m0 = mb * 128;
    const float* WT = g_WT + (size_t)dir * 300 * 1024;
    const float* bias = dir ? bbv : bf;
    int tid = threadIdx.x;
    int tw = tid & 15, tx = tid >> 4;
    uint64_t acc[8][4];
#pragma unroll
    for (int i = 0; i < 8; i++)
#pragma unroll
        for (int j = 0; j < 4; j++) acc[i][j] = 0ull;

    for (int kt = 0; kt < 15; kt++) {
        int k0 = kt * 20;
#pragma unroll
        for (int i = 0; i < 10; i++) {
            int idx = i * 256 + tid;
            int kk = idx >> 7, mm = idx & 127;
            Xs[idx] = g_xT[(size_t)(k0 + kk) * 8192 + m0 + mm];
            Ws[idx] = WT[(size_t)(k0 + kk) * 1024 + j0 + mm];
        }
        __syncthreads();
#pragma unroll 4
        for (int kk = 0; kk < 20; kk++) {
            float4 w0 = *(const float4*)&Ws[kk * 128 + tw * 8];
            float4 w1 = *(const float4*)&Ws[kk * 128 + tw * 8 + 4];
            ulonglong2 x01 = *(const ulonglong2*)&Xs[kk * 128 + tx * 8];
            ulonglong2 x23 = *(const ulonglong2*)&Xs[kk * 128 + tx * 8 + 4];
            uint64_t wd[8];
            wd[0] = pk2(w0.x, w0.x); wd[1] = pk2(w0.y, w0.y);
            wd[2] = pk2(w0.z, w0.z); wd[3] = pk2(w0.w, w0.w);
            wd[4] = pk2(w1.x, w1.x); wd[5] = pk2(w1.y, w1.y);
            wd[6] = pk2(w1.z, w1.z); wd[7] = pk2(w1.w, w1.w);
#pragma unroll
            for (int wn = 0; wn < 8; wn++) {
                acc[wn][0] = ffma2(wd[wn], x01.x, acc[wn][0]);
                acc[wn][1] = ffma2(wd[wn], x01.y, acc[wn][1]);
                acc[wn][2] = ffma2(wd[wn], x23.x, acc[wn][2]);
                acc[wn][3] = ffma2(wd[wn], x23.y, acc[wn][3]);
            }
        }
        __syncthreads();
    }
    // epilogue -> g_xg[t][dir][g][u][b]
    int t = mb * 2 + (tx >> 3);
    int bb = (tx & 7) * 8;
#pragma unroll
    for (int wn = 0; wn < 8; wn++) {
        int n = j0 + tw * 8 + wn;
        int g = n >> 8, u = n & 255;
        float bv = bias[n];
        uint64_t bd = pk2(bv, bv);
        uint64_t o0 = addx2(acc[wn][0], bd);
        uint64_t o1 = addx2(acc[wn][1], bd);
        uint64_t o2 = addx2(acc[wn][2], bd);
        uint64_t o3 = addx2(acc[wn][3], bd);
        float* op = &g_xg[(size_t)((t * 2 + dir) * 4 + g) * 16384 + u * 64 + bb];
        ulonglong2 s0; s0.x = o0; s0.y = o1;
        ulonglong2 s1; s1.x = o2; s1.y = o3;
        *(ulonglong2*)op = s0;
        *(ulonglong2*)(op + 4) = s1;
    }
}

// ---------------- kernel 4: persistent LSTM ----------------
// 128 blocks (dir, 4 units = 16 gate-rows), 256 threads.
// warp: bg = warp>>1 (batch group of 16), kh = warp&1 (k half).
// lane: uu = lane>>3 (unit), bp = lane&7 (batch pair) -> batches b0, b0+1.
// lane acc: 4 gates as f32x2 over the batch pair.
__global__ void __launch_bounds__(256, 1)
k_lstm_all(const float* __restrict__ Whf, const float* __restrict__ Whb) {
    extern __shared__ float sm[];
    uint64_t* wTd = (uint64_t*)sm;                     // [k][uu][g] dup, 4096 u64 = 32KB
    float* hsm = sm + 8192;                            // [k][b] 256*64 = 64KB
    uint64_t* red = (uint64_t*)(sm + 8192 + 16384);    // [bg][lane][g] 512 u64 = 4KB

    int bx = blockIdx.x;
    int dir = bx >> 6;
    int u0 = (bx & 63) * 4;
    const float* W = dir ? Whb : Whf;
    int tid = threadIdx.x;
    int warp = tid >> 5, lane = tid & 31;
    int bg = warp >> 1, kh = warp & 1;
    int uu = lane >> 3, bp = lane & 7;
    int b0 = (bg * 8 + bp) * 2;

    // build dup'd weights once: coalesced global, conflicted STS (one-time)
#pragma unroll
    for (int i = 0; i < 16; i++) {
        int idx = i * 256 + tid;
        int k = idx & 255;
        int ug = idx >> 8;              // 0..15
        int u2 = ug >> 2, g = ug & 3;
        float w = W[(size_t)(g * HH + u0 + u2) * HH + k];
        wTd[k * 16 + ug] = pk2(w, w);
    }
    __syncthreads();

    float c0 = 0.f, c1 = 0.f;
    unsigned goal = 0;
    unsigned int* ctr = &g_barD[dir];
    uint64_t* redp = red + (size_t)(bg * 32 + lane) * 4;

    for (int s = 0; s < LL; s++) {
        int t = dir ? (LL - 1 - s) : s;

        uint64_t xgp[4];
        if (kh == 0) {
#pragma unroll
            for (int g = 0; g < 4; g++)
                xgp[g] = *(const uint64_t*)&g_xg[(size_t)((t * 2 + dir) * 4 + g) * 16384 + (u0 + uu) * 64 + b0];
        }

        uint64_t a0 = 0ull, a1 = 0ull, a2 = 0ull, a3 = 0ull;
        if (s > 0) {
            const uint64_t* wp = wTd + kh * 2048 + uu * 4;
            const float* hp = hsm + kh * 8192 + b0;
#pragma unroll 8
            for (int kk = 0; kk < 128; kk++) {
                ulonglong2 wa = *(const ulonglong2*)wp;
                ulonglong2 wb = *(const ulonglong2*)(wp + 2);
                uint64_t hv = *(const uint64_t*)hp;
                a0 = ffma2(wa.x, hv, a0);
                a1 = ffma2(wa.y, hv, a1);
                a2 = ffma2(wb.x, hv, a2);
                a3 = ffma2(wb.y, hv, a3);
                wp += 16;
                hp += 64;
            }
        }
        if (kh == 1) {
            ulonglong2 s0; s0.x = a0; s0.y = a1;
            ulonglong2 s1; s1.x = a2; s1.y = a3;
            *(ulonglong2*)redp = s0;
            *(ulonglong2*)(redp + 2) = s1;
        }
        __syncthreads();
        if (kh == 0) {
            ulonglong2 r0 = *(const ulonglong2*)redp;
            ulonglong2 r1 = *(const ulonglong2*)(redp + 2);
            a0 = addx2(a0, r0.x); a1 = addx2(a1, r0.y);
            a2 = addx2(a2, r1.x); a3 = addx2(a3, r1.y);
            float2 gi = up2(addx2(a0, xgp[0]));
            float2 gf = up2(addx2(a1, xgp[1]));
            float2 gg = up2(addx2(a2, xgp[2]));
            float2 go = up2(addx2(a3, xgp[3]));
            float si0 = 1.f / (1.f + expf(-gi.x));
            float sf0 = 1.f / (1.f + expf(-gf.x));
            float so0 = 1.f / (1.f + expf(-go.x));
            c0 = sf0 * c0 + si0 * tanhf(gg.x);
            float h0 = so0 * tanhf(c0);
            float si1 = 1.f / (1.f + expf(-gi.y));
            float sf1 = 1.f / (1.f + expf(-gf.y));
            float so1 = 1.f / (1.f + expf(-go.y));
            c1 = sf1 * c1 + si1 * tanhf(gg.y);
            float h1 = so1 * tanhf(c1);
            *(uint64_t*)&g_hsT[(size_t)(t * 2 + dir) * 16384 + (u0 + uu) * 64 + b0] = pk2(h0, h1);
        }
        if (s < LL - 1) {
            __syncthreads();
            if (tid == 0) {
                asm volatile("red.release.gpu.global.add.u32 [%0], %1;" :: "l"(ctr), "r"(1u) : "memory");
                goal += 64u;
                unsigned v;
                while (1) {
                    asm volatile("ld.acquire.gpu.global.u32 %0, [%1];" : "=r"(v) : "l"(ctr) : "memory");
                    if (v >= goal) break;
                    __nanosleep(64);
                }
            }
            __syncthreads();
            const float4* srcp = (const float4*)(g_hsT + (size_t)(t * 2 + dir) * 16384);
            float4* dstp = (float4*)hsm;
#pragma unroll
            for (int i = 0; i < 16; i++) dstp[i * 256 + tid] = srcp[i * 256 + tid];
            __syncthreads();
        }
    }
}

// ---------------- kernel 5: projection GEMM  hs[8192,512] @ Wcat^T ----------------
__global__ void k_gemm2(const float* __restrict__ be, const float* __restrict__ ba) {
    __shared__ float Ash[16][64];
    __shared__ float Bsh[16][116];
    int t = blockIdx.x;
    const float* slabA = g_hsT + (size_t)t * 512 * 64;
    int tid = threadIdx.x;
    int tm = tid & 15, tn = tid >> 4;
    float acc[4][7] = {};
    for (int kt = 0; kt < 32; kt++) {
        int k0 = kt * 16;
        {
            int kk = tid >> 4, b4 = (tid & 15) * 4;
            *(float4*)&Ash[kk][b4] = *(const float4*)(slabA + (size_t)(k0 + kk) * 64 + b4);
        }
#pragma unroll
        for (int i = 0; i < 7; i++) {
            int idx = i * 256 + tid;
            int nn = idx >> 4, kk = idx & 15;
            Bsh[kk][nn] = g_Wcat[(size_t)nn * 512 + k0 + kk];
        }
        __syncthreads();
#pragma unroll
        for (int kk = 0; kk < 16; kk++) {
            float4 a = *(float4*)&Ash[kk][tm * 4];
#pragma unroll
            for (int j = 0; j < 7; j++) {
                float bv = Bsh[kk][tn * 7 + j];
                acc[0][j] += a.x * bv;
                acc[1][j] += a.y * bv;
                acc[2][j] += a.z * bv;
                acc[3][j] += a.w * bv;
            }
        }
        __syncthreads();
    }
#pragma unroll
    for (int i = 0; i < 4; i++) {
        int m = t * 64 + tm * 4 + i;
#pragma unroll
        for (int j = 0; j < 7; j++) {
            int n = tn * 7 + j;
            float v = acc[i][j];
            if (n < 34)       g_evbase[(size_t)m * NE + n]        = v + be[n];
            else if (n < 70)  g_base36[(size_t)m * NA + (n - 34)] = v + ba[n - 34];
            else if (n < 106) g_thadd [(size_t)m * NA + (n - 70)] = v;
        }
    }
}

// ---------------- kernel 6: event chains ----------------
__global__ void k_stageA(float* __restrict__ out_ev) {
    __shared__ float was[33 * 34];
    int tid = threadIdx.x;    // 256
    int b = tid >> 2, q = tid & 3;
    for (int i = tid; i < 33 * 34; i += 256) was[i] = g_WeGT[i];
    __syncthreads();
    int n0 = q * 9;
    int cnt = (q == 3) ? 7 : 9;
    float ctrg[9];
#pragma unroll
    for (int i = 0; i < 9; i++) ctrg[i] = 0.f;
    unsigned long long bits = 0ull;
    for (int t = 0; t < LL; t++) {
        const float* eb = &g_evbase[(size_t)(t * 64 + b) * NE + n0];
        float o[9];
        float bestv = -1e30f;
        int besti = 1000;
#pragma unroll
        for (int i = 0; i < 9; i++) {
            if (i < cnt) {
                o[i] = eb[i] + ctrg[i];
                if (o[i] > bestv) { bestv = o[i]; besti = n0 + i; }
            }
        }
#pragma unroll
        for (int off = 1; off < 4; off <<= 1) {
            float ov = __shfl_xor_sync(0xffffffffu, bestv, off, 4);
            int   oi = __shfl_xor_sync(0xffffffffu, besti, off, 4);
            if (ov > bestv || (ov == bestv && oi < besti)) { bestv = ov; besti = oi; }
        }
        float* ob = &out_ev[((size_t)b * LL + t) * NE + n0];
#pragma unroll
        for (int i = 0; i < 9; i++) if (i < cnt) ob[i] = o[i];
        if (q == 0) g_emask[b * LL + t] = (besti > 0) ? 1 : 0;
        if (besti > 0) {
            int j = besti - 1;
            if (!((bits >> j) & 1ull)) {
                bits |= 1ull << j;
#pragma unroll
                for (int i = 0; i < 9; i++) if (i < cnt) ctrg[i] += was[j * NE + n0 + i];
            }
        }
    }
}

// ---------------- kernel 7: argument chains, direct coalesced stores ----------------
__global__ void k_stageB(float* __restrict__ out_arg) {
    __shared__ float was[35 * 36];
    __shared__ unsigned char em[LL];
    int bx = blockIdx.x;          // 128 blocks
    int b = bx >> 1, ph = bx & 1;
    int tid = threadIdx.x;        // 256
    int p = tid >> 2;
    int pos = ph * 64 + p;
    int q = tid & 3;
    int n0 = q * 9;
    if (tid < LL) em[tid] = g_emask[b * LL + tid];
    for (int i = tid; i < 35 * 36; i += 256) was[i] = g_WaGT[i];
    __syncthreads();

    float base[9], C[9];
    const float* bp = &g_base36[(size_t)(pos * 64 + b) * NA + n0];
#pragma unroll
    for (int i = 0; i < 9; i++) { base[i] = bp[i]; C[i] = 0.f; }
    unsigned long long bits = 0ull;

    for (int t = 0; t < LL; t++) {
        const float* th = &g_thadd[(size_t)(t * 64 + b) * NA + n0];
        float o[9];
        float bestv = -1e30f;
        int besti = 1000;
#pragma unroll
        for (int i = 0; i < 9; i++) {
            o[i] = base[i] + C[i] + th[i];
            if (o[i] > bestv) { bestv = o[i]; besti = n0 + i; }
        }
#pragma unroll
        for (int off = 1; off < 4; off <<= 1) {
            float ov = __shfl_xor_sync(0xffffffffu, bestv, off, 4);
            int   oi = __shfl_xor_sync(0xffffffffu, besti, off, 4);
            if (ov > bestv || (ov == bestv && oi < besti)) { bestv = ov; besti = oi; }
        }
        float* op = &out_arg[((size_t)(b * LL + t) * LL + pos) * NA + n0];
#pragma unroll
        for (int i = 0; i < 9; i++) op[i] = o[i];
        if (em[t] && besti > 0) {
            int j = besti - 1;
            if (!((bits >> j) & 1ull)) {
                bits |= 1ull << j;
#pragma unroll
                for (int i = 0; i < 9; i++) C[i] += was[j * NA + n0 + i];
            }
        }
    }
}

// ---------------- launch ----------------
extern "C" void kernel_launch(void* const* d_in, const int* in_sizes, int n_in,
                              void* d_out, int out_size) {
    const int*   ids  = (const int*)  d_in[0];
    const float* emb  = (const float*)d_in[1];
    const float* Wihf = (const float*)d_in[2];
    const float* Whhf = (const float*)d_in[3];
    const float* bf   = (const float*)d_in[4];
    const float* Wihb = (const float*)d_in[5];
    const float* Whhb = (const float*)d_in[6];
    const float* bbv  = (const float*)d_in[7];
    const float* We   = (const float*)d_in[8];
    const float* be   = (const float*)d_in[9];
    const float* Wa   = (const float*)d_in[10];
    const float* ba   = (const float*)d_in[11];

    float* out_ev  = (float*)d_out;
    float* out_arg = out_ev + (size_t)BB * LL * NE;

    const int lstm_smem = 32768 + 65536 + 4096;   // 102400 B
    cudaFuncSetAttribute(k_lstm_all, cudaFuncAttributeMaxDynamicSharedMemorySize, lstm_smem);

    k_gather<<<LL, 256>>>(ids, emb);
    k_transW<<<dim3(32, 10, 2), dim3(32, 8)>>>(Wihf, Wihb);
    k_prep<<<64, 256>>>(We, Wa);
    k_gemm1<<<dim3(16, 64), 256>>>(bf, bbv);
    k_lstm_all<<<128, 256, lstm_smem>>>(Whhf, Whhb);
    k_gemm2<<<128, 256>>>(be, ba);
    k_stageA<<<1, 256>>>(out_ev);
    k_stageB<<<128, 256>>>(out_arg);
}

// round 6
// speedup vs baseline: 1.6234x; 1.0185x over previous
#include <cuda_runtime.h>
#include <math.h>
#include <stdint.h>

static constexpr int BB   = 64;
static constexpr int LL   = 128;
static constexpr int EMBD = 300;
static constexpr int HH   = 256;
static constexpr int NE   = 34;
static constexpr int NA   = 36;

// ---------------- scratch ----------------
__device__ float g_xT  [300 * 8192];              // [e][m=t*64+b]
__device__ float g_WT  [2 * 300 * 1024];          // [dir][k][row]
__device__ float g_xg  [LL * 2 * 4 * HH * BB];    // [t][dir][g][u][b]
__device__ float g_hsT [LL * 2 * HH * BB];        // [t][dir][u][b]
__device__ float g_evbase[LL * BB * NE];          // [t*64+b][34]
__device__ float g_base36[LL * BB * NA];          // [pos*64+b][36]
__device__ float g_thadd [LL * BB * NA];          // [t*64+b][36]
__device__ float g_Wcat [112 * 512];
__device__ float g_WeGT [33 * 34];
__device__ float g_WaGT [35 * 36];
__device__ unsigned char g_emask[BB * LL];
__device__ unsigned int g_barD[2];

// ---------------- f32x2 helpers ----------------
__device__ __forceinline__ uint64_t pk2(float x, float y) {
    uint64_t r; asm("mov.b64 %0,{%1,%2};" : "=l"(r) : "f"(x), "f"(y)); return r;
}
__device__ __forceinline__ uint64_t ffma2(uint64_t a, uint64_t b, uint64_t c) {
    uint64_t d; asm("fma.rn.f32x2 %0,%1,%2,%3;" : "=l"(d) : "l"(a), "l"(b), "l"(c)); return d;
}
__device__ __forceinline__ uint64_t addx2(uint64_t a, uint64_t b) {
    uint64_t d; asm("add.rn.f32x2 %0,%1,%2;" : "=l"(d) : "l"(a), "l"(b)); return d;
}
__device__ __forceinline__ float2 up2(uint64_t v) {
    float2 r; asm("mov.b64 {%0,%1},%2;" : "=f"(r.x), "=f"(r.y) : "l"(v)); return r;
}

// ---------------- kernel 1: embedding gather (transposed out) ----------------
__global__ void k_gather(const int* __restrict__ ids, const float* __restrict__ emb) {
    int t = blockIdx.x;               // 128 blocks, 256 threads
    int tid = threadIdx.x;
    int b = tid >> 2, q = tid & 3;
    int id = ids[b * LL + t];
    const float4* src = (const float4*)(emb + (size_t)id * EMBD);
#pragma unroll
    for (int j = 0; j < 19; j++) {
        int e4 = q + j * 4;
        if (e4 < 75) {
            float4 v = src[e4];
            int e = e4 * 4;
            size_t base = (size_t)e * 8192 + t * 64 + b;
            g_xT[base]          = v.x;
            g_xT[base + 8192]   = v.y;
            g_xT[base + 16384]  = v.z;
            g_xT[base + 24576]  = v.w;
        }
    }
}

// ---------------- kernel 1b: transpose W_ih (both dirs) ----------------
__global__ void k_transW(const float* __restrict__ Wf, const float* __restrict__ Wb) {
    __shared__ float ts[32][33];
    const float* W = blockIdx.z ? Wb : Wf;
    float* out = g_WT + (size_t)blockIdx.z * 300 * 1024;
    int n0 = blockIdx.x * 32, k0 = blockIdx.y * 32;
    int tx = threadIdx.x, ty = threadIdx.y;   // 32 x 8
#pragma unroll
    for (int r = 0; r < 4; r++) {
        int row = ty + r * 8;
        int k = k0 + tx;
        if (k < 300) ts[row][tx] = W[(size_t)(n0 + row) * 300 + k];
    }
    __syncthreads();
#pragma unroll
    for (int r = 0; r < 4; r++) {
        int row = ty + r * 8;
        int k = k0 + row;
        if (k < 300) out[(size_t)k * 1024 + n0 + tx] = ts[tx][row];
    }
}

// ---------------- kernel 2: pack decode weights + reset barriers ----------------
__global__ void k_prep(const float* __restrict__ We, const float* __restrict__ Wa) {
    if (blockIdx.x == 0 && threadIdx.x == 0) { g_barD[0] = 0u; g_barD[1] = 0u; }
    int tid = blockIdx.x * blockDim.x + threadIdx.x;
    int stride = gridDim.x * blockDim.x;
    for (int i = tid; i < 112 * 512; i += stride) {
        int n = i >> 9, k = i & 511;
        float v = 0.f;
        if (n < 34)       v = We[n * 545 + k];
        else if (n < 70)  v = Wa[(n - 34) * 1059 + k];
        else if (n < 106) v = Wa[(n - 70) * 1059 + 512 + k];
        g_Wcat[i] = v;
    }
    for (int i = tid; i < 33 * 34; i += stride) {
        int j = i / 34, e = i % 34;
        g_WeGT[i] = We[e * 545 + 512 + j];
    }
    for (int i = tid; i < 35 * 36; i += stride) {
        int j = i / 36, e = i % 36;
        g_WaGT[i] = Wa[e * 1059 + 1024 + j];
    }
}

// ---------------- kernel 3: input GEMM, 128x128 tiles, 8x8/thread, k-tile 30 ----------------
__global__ void k_gemm1(const float* __restrict__ bf, const float* __restrict__ bbv) {
    __shared__ float Xs[30 * 128];
    __shared__ float Ws[30 * 128];
    int nb = blockIdx.x;              // 0..15
    int mb = blockIdx.y;              // 0..63
    int dir = nb >> 3;
    int j0 = (nb & 7) * 128;
    int m0 = mb * 128;
    const float* WT = g_WT + (size_t)dir * 300 * 1024;
    const float* bias = dir ? bbv : bf;
    int tid = threadIdx.x;
    int tw = tid & 15, tx = tid >> 4;
    uint64_t acc[8][4];
#pragma unroll
    for (int i = 0; i < 8; i++)
#pragma unroll
        for (int j = 0; j < 4; j++) acc[i][j] = 0ull;

    for (int kt = 0; kt < 10; kt++) {
        int k0 = kt * 30;
#pragma unroll
        for (int i = 0; i < 15; i++) {
            int idx = i * 256 + tid;
            int kk = idx >> 7, mm = idx & 127;
            Xs[idx] = g_xT[(size_t)(k0 + kk) * 8192 + m0 + mm];
            Ws[idx] = WT[(size_t)(k0 + kk) * 1024 + j0 + mm];
        }
        __syncthreads();
#pragma unroll 5
        for (int kk = 0; kk < 30; kk++) {
            float4 w0 = *(const float4*)&Ws[kk * 128 + tw * 8];
            float4 w1 = *(const float4*)&Ws[kk * 128 + tw * 8 + 4];
            ulonglong2 x01 = *(const ulonglong2*)&Xs[kk * 128 + tx * 8];
            ulonglong2 x23 = *(const ulonglong2*)&Xs[kk * 128 + tx * 8 + 4];
            uint64_t wd[8];
            wd[0] = pk2(w0.x, w0.x); wd[1] = pk2(w0.y, w0.y);
            wd[2] = pk2(w0.z, w0.z); wd[3] = pk2(w0.w, w0.w);
            wd[4] = pk2(w1.x, w1.x); wd[5] = pk2(w1.y, w1.y);
            wd[6] = pk2(w1.z, w1.z); wd[7] = pk2(w1.w, w1.w);
#pragma unroll
            for (int wn = 0; wn < 8; wn++) {
                acc[wn][0] = ffma2(wd[wn], x01.x, acc[wn][0]);
                acc[wn][1] = ffma2(wd[wn], x01.y, acc[wn][1]);
                acc[wn][2] = ffma2(wd[wn], x23.x, acc[wn][2]);
                acc[wn][3] = ffma2(wd[wn], x23.y, acc[wn][3]);
            }
        }
        __syncthreads();
    }
    // epilogue -> g_xg[t][dir][g][u][b]
    int t = mb * 2 + (tx >> 3);
    int bb = (tx & 7) * 8;
#pragma unroll
    for (int wn = 0; wn < 8; wn++) {
        int n = j0 + tw * 8 + wn;
        int g = n >> 8, u = n & 255;
        float bv = bias[n];
        uint64_t bd = pk2(bv, bv);
        uint64_t o0 = addx2(acc[wn][0], bd);
        uint64_t o1 = addx2(acc[wn][1], bd);
        uint64_t o2 = addx2(acc[wn][2], bd);
        uint64_t o3 = addx2(acc[wn][3], bd);
        float* op = &g_xg[(size_t)((t * 2 + dir) * 4 + g) * 16384 + u * 64 + bb];
        ulonglong2 s0; s0.x = o0; s0.y = o1;
        ulonglong2 s1; s1.x = o2; s1.y = o3;
        *(ulonglong2*)op = s0;
        *(ulonglong2*)(op + 4) = s1;
    }
}

// ---------------- kernel 4: persistent LSTM, 512 threads, 4-way k-split ----------------
// 128 blocks (dir = bx>>6, 4 units). 16 warps: kh = warp&3 (k quarter), bg = warp>>2.
// lane: uu = lane>>3 (unit), bp = lane&7 -> batches b0 = bg*16 + bp*2 (+1).
__global__ void __launch_bounds__(512, 1)
k_lstm_all(const float* __restrict__ Whf, const float* __restrict__ Whb) {
    extern __shared__ float sm[];
    uint64_t* wTd = (uint64_t*)sm;                      // [k][ug] dup, 4096 u64 = 32KB
    float* hsm = sm + 8192;                             // [k][b] 256*64 = 64KB
    uint64_t* red = (uint64_t*)(sm + 8192 + 16384);     // [khm1][bg*32+lane][g] 1536 u64 = 12KB

    int bx = blockIdx.x;
    int dir = bx >> 6;
    int u0 = (bx & 63) * 4;
    const float* W = dir ? Whb : Whf;
    int tid = threadIdx.x;
    int warp = tid >> 5, lane = tid & 31;
    int kh = warp & 3, bg = warp >> 2;
    int uu = lane >> 3, bp = lane & 7;
    int b0 = bg * 16 + bp * 2;

    // build dup'd weights once
#pragma unroll
    for (int i = 0; i < 8; i++) {
        int idx = i * 512 + tid;        // 0..4095 = k*16 + ug
        int k = idx >> 4;
        int ug = idx & 15;
        int u2 = ug >> 2, g = ug & 3;
        float w = W[(size_t)(g * HH + u0 + u2) * HH + k];
        wTd[idx] = pk2(w, w);
    }
    __syncthreads();

    float c0 = 0.f, c1 = 0.f;
    unsigned goal = 0;
    unsigned int* ctr = &g_barD[dir];
    uint64_t* redw = red + (size_t)((kh - 1) * 128 + bg * 32 + lane) * 4;   // valid for kh>0
    uint64_t* redr = red + (size_t)(bg * 32 + lane) * 4;

    const uint64_t* wp0 = wTd + kh * 1024 + uu * 4;
    const float*    hp0 = hsm + kh * 64 * 64 + b0;

    for (int s = 0; s < LL; s++) {
        int t = dir ? (LL - 1 - s) : s;

        uint64_t xgp[4];
        if (kh == 0) {
#pragma unroll
            for (int g = 0; g < 4; g++)
                xgp[g] = *(const uint64_t*)&g_xg[(size_t)((t * 2 + dir) * 4 + g) * 16384 + (u0 + uu) * 64 + b0];
        }

        uint64_t a0 = 0ull, a1 = 0ull, a2 = 0ull, a3 = 0ull;
        if (s > 0) {
            const uint64_t* wp = wp0;
            const float* hp = hp0;
#pragma unroll 8
            for (int kk = 0; kk < 64; kk++) {
                ulonglong2 wa = *(const ulonglong2*)wp;
                ulonglong2 wb = *(const ulonglong2*)(wp + 2);
                uint64_t hv = *(const uint64_t*)hp;
                a0 = ffma2(wa.x, hv, a0);
                a1 = ffma2(wa.y, hv, a1);
                a2 = ffma2(wb.x, hv, a2);
                a3 = ffma2(wb.y, hv, a3);
                wp += 16;
                hp += 64;
            }
        }
        if (kh != 0) {
            ulonglong2 s0; s0.x = a0; s0.y = a1;
            ulonglong2 s1; s1.x = a2; s1.y = a3;
            *(ulonglong2*)redw = s0;
            *(ulonglong2*)(redw + 2) = s1;
        }
        __syncthreads();
        if (kh == 0) {
#pragma unroll
            for (int j = 0; j < 3; j++) {
                const uint64_t* rp = redr + (size_t)j * 512;
                ulonglong2 r0 = *(const ulonglong2*)rp;
                ulonglong2 r1 = *(const ulonglong2*)(rp + 2);
                a0 = addx2(a0, r0.x); a1 = addx2(a1, r0.y);
                a2 = addx2(a2, r1.x); a3 = addx2(a3, r1.y);
            }
            float2 gi = up2(addx2(a0, xgp[0]));
            float2 gf = up2(addx2(a1, xgp[1]));
            float2 gg = up2(addx2(a2, xgp[2]));
            float2 go = up2(addx2(a3, xgp[3]));
            float si0 = 1.f / (1.f + expf(-gi.x));
            float sf0 = 1.f / (1.f + expf(-gf.x));
            float so0 = 1.f / (1.f + expf(-go.x));
            c0 = sf0 * c0 + si0 * tanhf(gg.x);
            float h0 = so0 * tanhf(c0);
            float si1 = 1.f / (1.f + expf(-gi.y));
            float sf1 = 1.f / (1.f + expf(-gf.y));
            float so1 = 1.f / (1.f + expf(-go.y));
            c1 = sf1 * c1 + si1 * tanhf(gg.y);
            float h1 = so1 * tanhf(c1);
            *(uint64_t*)&g_hsT[(size_t)(t * 2 + dir) * 16384 + (u0 + uu) * 64 + b0] = pk2(h0, h1);
        }
        if (s < LL - 1) {
            __syncthreads();
            if (tid == 0) {
                asm volatile("red.release.gpu.global.add.u32 [%0], %1;" :: "l"(ctr), "r"(1u) : "memory");
                goal += 64u;
                unsigned v;
                while (1) {
                    asm volatile("ld.acquire.gpu.global.u32 %0, [%1];" : "=r"(v) : "l"(ctr) : "memory");
                    if (v >= goal) break;
                    __nanosleep(64);
                }
            }
            __syncthreads();
            const float4* srcp = (const float4*)(g_hsT + (size_t)(t * 2 + dir) * 16384);
            float4* dstp = (float4*)hsm;
#pragma unroll
            for (int i = 0; i < 8; i++) dstp[i * 512 + tid] = srcp[i * 512 + tid];
            __syncthreads();
        }
    }
}

// ---------------- kernel 5: projection GEMM  hs[8192,512] @ Wcat^T ----------------
__global__ void k_gemm2(const float* __restrict__ be, const float* __restrict__ ba) {
    __shared__ float Ash[16][64];
    __shared__ float Bsh[16][116];
    int t = blockIdx.x;
    const float* slabA = g_hsT + (size_t)t * 512 * 64;
    int tid = threadIdx.x;
    int tm = tid & 15, tn = tid >> 4;
    float acc[4][7] = {};
    for (int kt = 0; kt < 32; kt++) {
        int k0 = kt * 16;
        {
            int kk = tid >> 4, b4 = (tid & 15) * 4;
            *(float4*)&Ash[kk][b4] = *(const float4*)(slabA + (size_t)(k0 + kk) * 64 + b4);
        }
#pragma unroll
        for (int i = 0; i < 7; i++) {
            int idx = i * 256 + tid;
            int nn = idx >> 4, kk = idx & 15;
            Bsh[kk][nn] = g_Wcat[(size_t)nn * 512 + k0 + kk];
        }
        __syncthreads();
#pragma unroll
        for (int kk = 0; kk < 16; kk++) {
            float4 a = *(float4*)&Ash[kk][tm * 4];
#pragma unroll
            for (int j = 0; j < 7; j++) {
                float bv = Bsh[kk][tn * 7 + j];
                acc[0][j] += a.x * bv;
                acc[1][j] += a.y * bv;
                acc[2][j] += a.z * bv;
                acc[3][j] += a.w * bv;
            }
        }
        __syncthreads();
    }
#pragma unroll
    for (int i = 0; i < 4; i++) {
        int m = t * 64 + tm * 4 + i;
#pragma unroll
        for (int j = 0; j < 7; j++) {
            int n = tn * 7 + j;
            float v = acc[i][j];
            if (n < 34)       g_evbase[(size_t)m * NE + n]        = v + be[n];
            else if (n < 70)  g_base36[(size_t)m * NA + (n - 34)] = v + ba[n - 34];
            else if (n < 106) g_thadd [(size_t)m * NA + (n - 70)] = v;
        }
    }
}

// ---------------- kernel 6: event chains ----------------
__global__ void k_stageA(float* __restrict__ out_ev) {
    __shared__ float was[33 * 34];
    int tid = threadIdx.x;    // 256
    int b = tid >> 2, q = tid & 3;
    for (int i = tid; i < 33 * 34; i += 256) was[i] = g_WeGT[i];
    __syncthreads();
    int n0 = q * 9;
    int cnt = (q == 3) ? 7 : 9;
    float ctrg[9];
#pragma unroll
    for (int i = 0; i < 9; i++) ctrg[i] = 0.f;
    unsigned long long bits = 0ull;
    for (int t = 0; t < LL; t++) {
        const float* eb = &g_evbase[(size_t)(t * 64 + b) * NE + n0];
        float o[9];
        float bestv = -1e30f;
        int besti = 1000;
#pragma unroll
        for (int i = 0; i < 9; i++) {
            if (i < cnt) {
                o[i] = eb[i] + ctrg[i];
                if (o[i] > bestv) { bestv = o[i]; besti = n0 + i; }
            }
        }
#pragma unroll
        for (int off = 1; off < 4; off <<= 1) {
            float ov = __shfl_xor_sync(0xffffffffu, bestv, off, 4);
            int   oi = __shfl_xor_sync(0xffffffffu, besti, off, 4);
            if (ov > bestv || (ov == bestv && oi < besti)) { bestv = ov; besti = oi; }
        }
        float* ob = &out_ev[((size_t)b * LL + t) * NE + n0];
#pragma unroll
        for (int i = 0; i < 9; i++) if (i < cnt) ob[i] = o[i];
        if (q == 0) g_emask[b * LL + t] = (besti > 0) ? 1 : 0;
        if (besti > 0) {
            int j = besti - 1;
            if (!((bits >> j) & 1ull)) {
                bits |= 1ull << j;
#pragma unroll
                for (int i = 0; i < 9; i++) if (i < cnt) ctrg[i] += was[j * NE + n0 + i];
            }
        }
    }
}

// ---------------- kernel 7: argument chains ----------------
__global__ void k_stageB(float* __restrict__ out_arg) {
    __shared__ float was[35 * 36];
    __shared__ unsigned char em[LL];
    int bx = blockIdx.x;          // 128 blocks
    int b = bx >> 1, ph = bx & 1;
    int tid = threadIdx.x;        // 256
    int p = tid >> 2;
    int pos = ph * 64 + p;
    int q = tid & 3;
    int n0 = q * 9;
    if (tid < LL) em[tid] = g_emask[b * LL + tid];
    for (int i = tid; i < 35 * 36; i += 256) was[i] = g_WaGT[i];
    __syncthreads();

    float base[9], C[9];
    const float* bp = &g_base36[(size_t)(pos * 64 + b) * NA + n0];
#pragma unroll
    for (int i = 0; i < 9; i++) { base[i] = bp[i]; C[i] = 0.f; }
    unsigned long long bits = 0ull;

    for (int t = 0; t < LL; t++) {
        const float* th = &g_thadd[(size_t)(t * 64 + b) * NA + n0];
        float o[9];
        float bestv = -1e30f;
        int besti = 1000;
#pragma unroll
        for (int i = 0; i < 9; i++) {
            o[i] = base[i] + C[i] + th[i];
            if (o[i] > bestv) { bestv = o[i]; besti = n0 + i; }
        }
#pragma unroll
        for (int off = 1; off < 4; off <<= 1) {
            float ov = __shfl_xor_sync(0xffffffffu, bestv, off, 4);
            int   oi = __shfl_xor_sync(0xffffffffu, besti, off, 4);
            if (ov > bestv || (ov == bestv && oi < besti)) { bestv = ov; besti = oi; }
        }
        float* op = &out_arg[((size_t)(b * LL + t) * LL + pos) * NA + n0];
#pragma unroll
        for (int i = 0; i < 9; i++) op[i] = o[i];
        if (em[t] && besti > 0) {
            int j = besti - 1;
            if (!((bits >> j) & 1ull)) {
                bits |= 1ull << j;
#pragma unroll
                for (int i = 0; i < 9; i++) C[i] += was[j * NA + n0 + i];
            }
        }
    }
}

// ---------------- launch ----------------
extern "C" void kernel_launch(void* const* d_in, const int* in_sizes, int n_in,
                              void* d_out, int out_size) {
    const int*   ids  = (const int*)  d_in[0];
    const float* emb  = (const float*)d_in[1];
    const float* Wihf = (const float*)d_in[2];
    const float* Whhf = (const float*)d_in[3];
    const float* bf   = (const float*)d_in[4];
    const float* Wihb = (const float*)d_in[5];
    const float* Whhb = (const float*)d_in[6];
    const float* bbv  = (const float*)d_in[7];
    const float* We   = (const float*)d_in[8];
    const float* be   = (const float*)d_in[9];
    const float* Wa   = (const float*)d_in[10];
    const float* ba   = (const float*)d_in[11];

    float* out_ev  = (float*)d_out;
    float* out_arg = out_ev + (size_t)BB * LL * NE;

    const int lstm_smem = 32768 + 65536 + 12288;   // 110592 B
    cudaFuncSetAttribute(k_lstm_all, cudaFuncAttributeMaxDynamicSharedMemorySize, lstm_smem);

    k_gather<<<LL, 256>>>(ids, emb);
    k_transW<<<dim3(32, 10, 2), dim3(32, 8)>>>(Wihf, Wihb);
    k_prep<<<64, 256>>>(We, Wa);
    k_gemm1<<<dim3(16, 64), 256>>>(bf, bbv);
    k_lstm_all<<<128, 512, lstm_smem>>>(Whhf, Whhb);
    k_gemm2<<<128, 256>>>(be, ba);
    k_stageA<<<1, 256>>>(out_ev);
    k_stageB<<<128, 256>>>(out_arg);
}